// round 3
// baseline (speedup 1.0000x reference)
#include <cuda_runtime.h>
#include <cstdint>

// Shape (fixed): u[B=16, T=1024, H=2048] f32, alpha[H], beta[H], seed int32
#define BB 16
#define TT 1024
#define HH 2048
#define HC 8            // channels per CTA
#define NTHR 256

// Row offsets of each tree level (level l has 1024>>l rows)
__device__ __constant__ int OFFC[12] = {0,1024,1536,1792,1920,1984,2016,2032,2040,2044,2046,2047};

#define SMEM_FLOATS (2047*HC + 12*HC)
#define SMEM_BYTES  (SMEM_FLOATS * 4)

__device__ __forceinline__ unsigned rotl32(unsigned x, int r) {
    return __funnelshift_l(x, x, r);
}

// XLA f32 tanh (Eigen generic_fast_tanh_float). XLA emits plain fmul/fadd (no
// contraction) and IEEE div; replicate with explicit intrinsics.
__device__ __forceinline__ float tanh_xla(float x) {
    float ax = fabsf(x);
    float xc = fminf(fmaxf(x, -7.90531110763549805f), 7.90531110763549805f);
    float x2 = __fmul_rn(xc, xc);
    float np = __fadd_rn(__fmul_rn(x2, -2.76076847742355e-16f), 2.00018790482477e-13f);
    np = __fadd_rn(__fmul_rn(x2, np), -8.60467152213735e-11f);
    np = __fadd_rn(__fmul_rn(x2, np),  5.12229709037114e-08f);
    np = __fadd_rn(__fmul_rn(x2, np),  1.48572235717979e-05f);
    np = __fadd_rn(__fmul_rn(x2, np),  6.37261928875436e-04f);
    np = __fadd_rn(__fmul_rn(x2, np),  4.89352455891786e-03f);
    float num = __fmul_rn(xc, np);
    float dp = __fadd_rn(__fmul_rn(x2, 1.19825839466702e-06f), 1.18534705686654e-04f);
    dp = __fadd_rn(__fmul_rn(x2, dp), 2.26843463243900e-03f);
    dp = __fadd_rn(__fmul_rn(x2, dp), 4.89352518554385e-03f);
    float t = __fdiv_rn(num, dp);
    return (ax < 0.0004f) ? x : t;
}

__device__ __forceinline__ float cos_accurate(float x) {
#ifdef __FAST_MATH__
    return (float)cos((double)x);   // avoid __cosf approximation under fast-math
#else
    return cosf(x);                 // == libdevice __nv_cosf == XLA lowering
#endif
}

// One jax.lax.associative_scan tree (up-sweep + down-sweep) over L0 = S[0..1023][HC].
// AA[l*HC + c] = per-level decay power A_l = tau^(2^l) (repeated squaring, exact).
// All combines use separate mul/add (no FMA) to match XLA's emitted LLVM IR.
__device__ void scan_tree(float* S, const float* AA) {
    const int tid = threadIdx.x;
    // Up-sweep: U_{l+1}[k] = A_l*U_l[2k] + U_l[2k+1]
    #pragma unroll
    for (int l = 0; l < 10; l++) {
        const int srcOff = OFFC[l], dstOff = OFFC[l+1];
        const int cnt = (512 >> l) * HC;
        for (int idx = tid; idx < cnt; idx += NTHR) {
            int k = idx >> 3, c = idx & (HC-1);
            float a  = AA[l*HC + c];
            float s0 = S[(srcOff + 2*k    )*HC + c];
            float s1 = S[(srcOff + 2*k + 1)*HC + c];
            S[(dstOff + k)*HC + c] = __fadd_rn(__fmul_rn(a, s0), s1);
        }
        __syncthreads();
    }
    // Down-sweep (in place): R_l[2k+1] = R_{l+1}[k];
    // R_l[2k] = (k==0) ? U_l[0] : A_l*R_{l+1}[k-1] + U_l[2k]
    #pragma unroll
    for (int l = 9; l >= 0; l--) {
        const int lOff = OFFC[l], upOff = OFFC[l+1];
        const int cnt = (512 >> l) * HC;
        for (int idx = tid; idx < cnt; idx += NTHR) {
            int k = idx >> 3, c = idx & (HC-1);
            float r = S[(upOff + k)*HC + c];
            if (k > 0) {
                float rprev = S[(upOff + k - 1)*HC + c];
                float a = AA[l*HC + c];
                float u0 = S[(lOff + 2*k)*HC + c];
                S[(lOff + 2*k)*HC + c] = __fadd_rn(__fmul_rn(a, rprev), u0);
            }
            S[(lOff + 2*k + 1)*HC + c] = r;
        }
        __syncthreads();
    }
}

__global__ void __launch_bounds__(NTHR)
cubalif_kernel(const float* __restrict__ u,
               const float* __restrict__ alpha,
               const float* __restrict__ beta,
               const int*   __restrict__ seedp,
               float* __restrict__ out) {
    extern __shared__ float S[];                 // [2047*HC] tree + [12*HC] powers
    float* AA = S + 2047*HC;

    const int tid = threadIdx.x;
    const int blocksPerB = HH / HC;              // 256
    const int b  = blockIdx.x / blocksPerB;
    const int h0 = (blockIdx.x % blocksPerB) * HC;

    // ---- load u tile [T][HC] into L0 via float4 ----
    const float4* up = reinterpret_cast<const float4*>(u + ((size_t)b * TT) * HH + h0);
    float4* S4 = reinterpret_cast<float4*>(S);
    #pragma unroll 4
    for (int i4 = tid; i4 < TT * HC / 4; i4 += NTHR) {
        int t = i4 >> 1;            // HC/4 = 2 quads per row
        int q = i4 & 1;
        S4[i4] = up[(size_t)t * (HH/4) + q];
    }

    // ---- alpha powers: A_0 = clip(alpha,0,1); A_{l+1} = A_l*A_l ----
    if (tid < HC) {
        float a = fminf(fmaxf(alpha[h0 + tid], 0.0f), 1.0f);
        AA[tid] = a;
        #pragma unroll
        for (int l = 1; l <= 10; l++) { a = __fmul_rn(a, a); AA[l*HC + tid] = a; }
    }
    __syncthreads();

    scan_tree(S, AA);            // L0 <- x (synaptic current scan)

    if (tid < HC) {
        float bb = fminf(fmaxf(beta[h0 + tid], 0.0f), 1.0f);
        AA[tid] = bb;
        #pragma unroll
        for (int l = 1; l <= 10; l++) { bb = __fmul_rn(bb, bb); AA[l*HC + tid] = bb; }
    }
    __syncthreads();

    scan_tree(S, AA);            // L0 <- V (membrane potential scan)

    // ---- elementwise: p, threefry (partitionable), bernoulli ----
    const unsigned k2   = (unsigned)seedp[0];    // key = (0, seed): ks0=0
    const unsigned ks1  = k2;
    const unsigned ks2v = k2 ^ 0x1BD11BDAu;

    #pragma unroll 2
    for (int idx = tid; idx < TT * HC; idx += NTHR) {
        int t = idx >> 3, c = idx & (HC-1);
        float V = S[idx];
        float U = __fadd_rn(V, -1.0f);                        // V - THRESHOLD
        float cv  = cos_accurate(__fmul_rn(6.2831855f, U));   // cos(f32(2*pi) * U)
        // XLA logistic(100*U) = 0.5 + 0.5*tanh(0.5*100*U) = 0.5 + 0.5*tanh(50*U)
        float th  = tanh_xla(__fmul_rn(50.0f, U));
        float sig = __fadd_rn(__fmul_rn(0.5f, th), 0.5f);
        float p   = fmaxf(__fmul_rn(cv, sig), 0.0f);

        unsigned gi = ((unsigned)(b * TT + t)) * (unsigned)HH + (unsigned)(h0 + c);

        // threefry2x32(key=(0,seed), counts=(hi=0, lo=gi)); fold: out0 ^ out1
        unsigned x0 = 0u;             // hi + ks0
        unsigned x1 = gi + ks1;       // lo + ks1
        #define TFR(r) { x0 += x1; x1 = rotl32(x1, (r)); x1 ^= x0; }
        TFR(13) TFR(15) TFR(26) TFR(6)   x0 += ks1;  x1 += ks2v + 1u;
        TFR(17) TFR(29) TFR(16) TFR(24)  x0 += ks2v; x1 += 2u;          // +ks0(=0)
        TFR(13) TFR(15) TFR(26) TFR(6)                x1 += ks1 + 3u;   // x0+=ks0(=0)
        TFR(17) TFR(29) TFR(16) TFR(24)  x0 += ks1;  x1 += ks2v + 4u;
        TFR(13) TFR(15) TFR(26) TFR(6)   x0 += ks2v; x1 += 5u;          // +ks0(=0)
        #undef TFR
        unsigned bits = x0 ^ x1;

        float uf = __fadd_rn(__uint_as_float((bits >> 9) | 0x3F800000u), -1.0f);
        out[gi] = (uf < p) ? 1.0f : 0.0f;
    }
}

extern "C" void kernel_launch(void* const* d_in, const int* in_sizes, int n_in,
                              void* d_out, int out_size) {
    const float* u     = (const float*)d_in[0];
    const float* alpha = (const float*)d_in[1];
    const float* beta  = (const float*)d_in[2];
    const int*   seed  = (const int*)d_in[3];
    float* out = (float*)d_out;
    (void)in_sizes; (void)n_in; (void)out_size;

    cudaFuncSetAttribute(cubalif_kernel,
                         cudaFuncAttributeMaxDynamicSharedMemorySize, SMEM_BYTES);

    dim3 grid(BB * (HH / HC));   // 4096 CTAs
    cubalif_kernel<<<grid, NTHR, SMEM_BYTES>>>(u, alpha, beta, seed, out);
}

// round 4
// speedup vs baseline: 1.6300x; 1.6300x over previous
#include <cuda_runtime.h>
#include <cstdint>

// Shape (fixed): u[B=16, T=1024, H=2048] f32, alpha[H], beta[H], seed int32
#define BB 16
#define TT 1024
#define HH 2048
#define HC 8            // channels per CTA (= warps per CTA)
#define NTHR 256
#define FULLM 0xFFFFFFFFu

#define TILE_FLOATS (TT * HC)    // 8192 floats = 32 KB

// XOR-swizzled tile layout: block of 32 t-rows = 256 floats; low-5 bits of the
// intra-block offset XORed with the block index (t>>5). Guarantees the
// per-warp column reads (lane = t>>5 varies, j,c fixed) hit 32 distinct banks.
__device__ __forceinline__ int swz(int t, int c) {
    int L = t >> 5;
    return (L << 8) + ((((t & 31) << 3) + c) ^ L);
}

__device__ __forceinline__ unsigned rotl32(unsigned x, int r) {
    return __funnelshift_l(x, x, r);
}

// XLA f32 tanh (Eigen generic_fast_tanh_float), plain mul/add (no contraction).
__device__ __forceinline__ float tanh_xla(float x) {
    float ax = fabsf(x);
    float xc = fminf(fmaxf(x, -7.90531110763549805f), 7.90531110763549805f);
    float x2 = __fmul_rn(xc, xc);
    float np = __fadd_rn(__fmul_rn(x2, -2.76076847742355e-16f), 2.00018790482477e-13f);
    np = __fadd_rn(__fmul_rn(x2, np), -8.60467152213735e-11f);
    np = __fadd_rn(__fmul_rn(x2, np),  5.12229709037114e-08f);
    np = __fadd_rn(__fmul_rn(x2, np),  1.48572235717979e-05f);
    np = __fadd_rn(__fmul_rn(x2, np),  6.37261928875436e-04f);
    np = __fadd_rn(__fmul_rn(x2, np),  4.89352455891786e-03f);
    float num = __fmul_rn(xc, np);
    float dp = __fadd_rn(__fmul_rn(x2, 1.19825839466702e-06f), 1.18534705686654e-04f);
    dp = __fadd_rn(__fmul_rn(x2, dp), 2.26843463243900e-03f);
    dp = __fadd_rn(__fmul_rn(x2, dp), 4.89352518554385e-03f);
    float t = __fdiv_rn(num, dp);
    return (ax < 0.0004f) ? x : t;
}

// The exact jax.lax.associative_scan tree over 1024 elements per channel,
// executed as: in-place register Blelloch on each lane's 32 elements
// (levels 0-4), warp-shuffle Blelloch across lanes (levels 5-9), then the
// in-place down-sweep with cross-chunk prefix P. Every combine is
// A_l * left + right with A_l = a^(2^l) from the same squaring chain JAX
// computes — identical operations, identical rounding, different schedule.
__device__ __forceinline__ void tree_scan(float (&v)[32], const float* A, int lane) {
    // local up-sweep: v[p] (odd child) <- A_s * v[p - 2^s] + v[p]
    #pragma unroll
    for (int s = 0; s < 5; s++) {
        const int h = 1 << s, st = h << 1;
        #pragma unroll
        for (int p = st - 1; p < 32; p += st)
            v[p] = __fadd_rn(__fmul_rn(A[s], v[p - h]), v[p]);
    }
    float w = v[31];                      // chunk total = U_5[lane]
    // warp up-sweep: levels 5..9
    #pragma unroll
    for (int m = 0; m < 5; m++) {
        float t = __shfl_up_sync(FULLM, w, 1 << m);
        if ((lane & ((2 << m) - 1)) == ((2 << m) - 1))
            w = __fadd_rn(__fmul_rn(A[5 + m], t), w);
    }
    // warp down-sweep: levels 8..5 (level 9's even node is a no-op)
    #pragma unroll
    for (int m = 3; m >= 0; m--) {
        float t = __shfl_up_sync(FULLM, w, 1 << m);
        if (((lane & ((2 << m) - 1)) == ((1 << m) - 1)) && (lane >= (2 << m)))
            w = __fadd_rn(__fmul_rn(A[5 + m], t), w);
    }
    float P = __shfl_up_sync(FULLM, w, 1);   // R_5[lane-1]
    if (lane == 0) P = 0.0f;                 // A*0+U == U (sign-of-zero benign)
    v[31] = w;                               // R_5[lane]
    // local down-sweep: even node at p=k*2^{s+1}+2^s-1; left prefix is P for
    // k==0 (prev chunk's final inclusive value works at every level).
    #pragma unroll
    for (int s = 4; s >= 0; s--) {
        const int h = 1 << s, st = h << 1;
        #pragma unroll
        for (int p = h - 1; p < 32; p += st) {
            float left = (p < st) ? P : v[p - h];
            v[p] = __fadd_rn(__fmul_rn(A[s], left), v[p]);
        }
    }
}

__global__ void __launch_bounds__(NTHR)
cubalif_kernel(const float* __restrict__ u,
               const float* __restrict__ alpha,
               const float* __restrict__ beta,
               const int*   __restrict__ seedp,
               float* __restrict__ out) {
    __shared__ float S[TILE_FLOATS];

    const int tid  = threadIdx.x;
    const int lane = tid & 31;
    const int wrp  = tid >> 5;            // channel within 8-group
    const int b    = blockIdx.x >> 8;
    const int h0   = (blockIdx.x & 255) * HC;

    // ---- stage u tile [T][8] into swizzled smem (coalesced float4 loads) ----
    const float4* up4 = reinterpret_cast<const float4*>(u + ((size_t)b * TT) * HH + h0);
    #pragma unroll
    for (int k = 0; k < TILE_FLOATS / 4 / NTHR; k++) {   // 8 iters
        int i4 = k * NTHR + tid;
        int t = i4 >> 1, q = i4 & 1;
        float4 d = up4[(size_t)t * (HH / 4) + q];
        int c0 = q * 4;
        S[swz(t, c0 + 0)] = d.x;
        S[swz(t, c0 + 1)] = d.y;
        S[swz(t, c0 + 2)] = d.z;
        S[swz(t, c0 + 3)] = d.w;
    }
    __syncthreads();

    // ---- gather this thread's 32 time steps of channel wrp (conflict-free) ----
    float v[32];
    #pragma unroll
    for (int j = 0; j < 32; j++)
        v[j] = S[(lane << 8) + (((j << 3) + wrp) ^ lane)];

    // ---- decay powers A_l = tau^(2^l), squaring chain (exact as JAX) ----
    float A[10];
    A[0] = fminf(fmaxf(alpha[h0 + wrp], 0.0f), 1.0f);
    #pragma unroll
    for (int s = 1; s < 10; s++) A[s] = __fmul_rn(A[s - 1], A[s - 1]);
    tree_scan(v, A, lane);                // v <- x (synaptic current)

    A[0] = fminf(fmaxf(beta[h0 + wrp], 0.0f), 1.0f);
    #pragma unroll
    for (int s = 1; s < 10; s++) A[s] = __fmul_rn(A[s - 1], A[s - 1]);
    tree_scan(v, A, lane);                // v <- V (membrane potential)

    // ---- write V back (each warp touches only its own channel's slots) ----
    #pragma unroll
    for (int j = 0; j < 32; j++)
        S[(lane << 8) + (((j << 3) + wrp) ^ lane)] = v[j];
    __syncthreads();

    // ---- elementwise + threefry + output in flat coalesced layout ----
    const unsigned k2   = (unsigned)seedp[0];    // key=(0,seed): ks0=0
    const unsigned ks1  = k2;
    const unsigned ks2v = k2 ^ 0x1BD11BDAu;
    float* outp = out + ((size_t)b * TT) * HH + h0;

    #pragma unroll 2
    for (int k = 0; k < TILE_FLOATS / 4 / NTHR; k++) {
        int i4 = k * NTHR + tid;
        int t = i4 >> 1, q = i4 & 1;
        int c0 = q * 4;
        float r[4];
        #pragma unroll
        for (int i = 0; i < 4; i++) {
            float V = S[swz(t, c0 + i)];
            float U = __fadd_rn(V, -1.0f);                       // V - THRESHOLD
            float cv  = cosf(__fmul_rn(6.2831855f, U));          // cos(f32(2pi)*U)
            float th  = tanh_xla(__fmul_rn(50.0f, U));           // logistic(100U)
            float sig = __fadd_rn(__fmul_rn(0.5f, th), 0.5f);
            float p   = fmaxf(__fmul_rn(cv, sig), 0.0f);

            unsigned gi = (unsigned)(b * TT + t) * (unsigned)HH + (unsigned)(h0 + c0 + i);
            // threefry2x32(key=(0,seed), counts=(0, gi)); fold out0^out1
            unsigned x0 = 0u;
            unsigned x1 = gi + ks1;
            #define TFR(r_) { x0 += x1; x1 = rotl32(x1, (r_)); x1 ^= x0; }
            TFR(13) TFR(15) TFR(26) TFR(6)   x0 += ks1;  x1 += ks2v + 1u;
            TFR(17) TFR(29) TFR(16) TFR(24)  x0 += ks2v; x1 += 2u;
            TFR(13) TFR(15) TFR(26) TFR(6)                x1 += ks1 + 3u;
            TFR(17) TFR(29) TFR(16) TFR(24)  x0 += ks1;  x1 += ks2v + 4u;
            TFR(13) TFR(15) TFR(26) TFR(6)   x0 += ks2v; x1 += 5u;
            #undef TFR
            unsigned bits = x0 ^ x1;
            float uf = __fadd_rn(__uint_as_float((bits >> 9) | 0x3F800000u), -1.0f);
            r[i] = (uf < p) ? 1.0f : 0.0f;
        }
        *reinterpret_cast<float4*>(outp + (size_t)t * HH + c0) =
            make_float4(r[0], r[1], r[2], r[3]);
    }
}

extern "C" void kernel_launch(void* const* d_in, const int* in_sizes, int n_in,
                              void* d_out, int out_size) {
    const float* u     = (const float*)d_in[0];
    const float* alpha = (const float*)d_in[1];
    const float* beta  = (const float*)d_in[2];
    const int*   seed  = (const int*)d_in[3];
    float* out = (float*)d_out;
    (void)in_sizes; (void)n_in; (void)out_size;

    dim3 grid(BB * (HH / HC));   // 4096 CTAs
    cubalif_kernel<<<grid, NTHR>>>(u, alpha, beta, seed, out);
}

// round 5
// speedup vs baseline: 1.6323x; 1.0014x over previous
#include <cuda_runtime.h>
#include <cstdint>

// Shape (fixed): u[B=16, T=1024, H=2048] f32, alpha[H], beta[H], seed int32
#define BB 16
#define TT 1024
#define HH 2048
#define HC 8            // channels per CTA (= warps per CTA)
#define NTHR 256
#define FULLM 0xFFFFFFFFu

#define TILE_FLOATS (TT * HC)    // 8192 floats = 32 KB

// XOR-swizzled tile layout (see R4): conflict-free column gathers.
__device__ __forceinline__ int swz(int t, int c) {
    int L = t >> 5;
    return (L << 8) + ((((t & 31) << 3) + c) ^ L);
}

__device__ __forceinline__ unsigned rotl32(unsigned x, int r) {
    return __funnelshift_l(x, x, r);
}

// Integer add routed to the FMA pipe as IMAD: a*one + b, with `one` an opaque
// kernel parameter (=1) that ptxas cannot constant-fold. Bit-exact.
__device__ __forceinline__ unsigned addi(unsigned a, unsigned one, unsigned b) {
    unsigned r;
    asm("mad.lo.u32 %0, %1, %2, %3;" : "=r"(r) : "r"(a), "r"(one), "r"(b));
    return r;
}

// XLA f32 tanh (Eigen generic_fast_tanh_float), plain mul/add (no contraction).
__device__ __forceinline__ float tanh_xla(float x) {
    float ax = fabsf(x);
    float xc = fminf(fmaxf(x, -7.90531110763549805f), 7.90531110763549805f);
    float x2 = __fmul_rn(xc, xc);
    float np = __fadd_rn(__fmul_rn(x2, -2.76076847742355e-16f), 2.00018790482477e-13f);
    np = __fadd_rn(__fmul_rn(x2, np), -8.60467152213735e-11f);
    np = __fadd_rn(__fmul_rn(x2, np),  5.12229709037114e-08f);
    np = __fadd_rn(__fmul_rn(x2, np),  1.48572235717979e-05f);
    np = __fadd_rn(__fmul_rn(x2, np),  6.37261928875436e-04f);
    np = __fadd_rn(__fmul_rn(x2, np),  4.89352455891786e-03f);
    float num = __fmul_rn(xc, np);
    float dp = __fadd_rn(__fmul_rn(x2, 1.19825839466702e-06f), 1.18534705686654e-04f);
    dp = __fadd_rn(__fmul_rn(x2, dp), 2.26843463243900e-03f);
    dp = __fadd_rn(__fmul_rn(x2, dp), 4.89352518554385e-03f);
    float t = __fdiv_rn(num, dp);
    return (ax < 0.0004f) ? x : t;
}

// Exact jax.lax.associative_scan tree over 1024 elems/channel:
// in-place register Blelloch (levels 0-4) + warp-shuffle Blelloch (5-9).
// Identical combines/rounding to JAX; only the schedule differs.
__device__ __forceinline__ void tree_scan(float (&v)[32], const float* A, int lane) {
    #pragma unroll
    for (int s = 0; s < 5; s++) {
        const int h = 1 << s, st = h << 1;
        #pragma unroll
        for (int p = st - 1; p < 32; p += st)
            v[p] = __fadd_rn(__fmul_rn(A[s], v[p - h]), v[p]);
    }
    float w = v[31];
    #pragma unroll
    for (int m = 0; m < 5; m++) {
        float t = __shfl_up_sync(FULLM, w, 1 << m);
        if ((lane & ((2 << m) - 1)) == ((2 << m) - 1))
            w = __fadd_rn(__fmul_rn(A[5 + m], t), w);
    }
    #pragma unroll
    for (int m = 3; m >= 0; m--) {
        float t = __shfl_up_sync(FULLM, w, 1 << m);
        if (((lane & ((2 << m) - 1)) == ((1 << m) - 1)) && (lane >= (2 << m)))
            w = __fadd_rn(__fmul_rn(A[5 + m], t), w);
    }
    float P = __shfl_up_sync(FULLM, w, 1);
    if (lane == 0) P = 0.0f;
    v[31] = w;
    #pragma unroll
    for (int s = 4; s >= 0; s--) {
        const int h = 1 << s, st = h << 1;
        #pragma unroll
        for (int p = h - 1; p < 32; p += st) {
            float left = (p < st) ? P : v[p - h];
            v[p] = __fadd_rn(__fmul_rn(A[s], left), v[p]);
        }
    }
}

__global__ void __launch_bounds__(NTHR)
cubalif_kernel(const float* __restrict__ u,
               const float* __restrict__ alpha,
               const float* __restrict__ beta,
               const int*   __restrict__ seedp,
               float* __restrict__ out,
               unsigned one) {
    __shared__ float S[TILE_FLOATS];

    const int tid  = threadIdx.x;
    const int lane = tid & 31;
    const int wrp  = tid >> 5;            // channel within 8-group
    const int b    = blockIdx.x >> 8;
    const int h0   = (blockIdx.x & 255) * HC;

    // ---- stage u tile [T][8] into swizzled smem (coalesced float4 loads) ----
    const float4* up4 = reinterpret_cast<const float4*>(u + ((size_t)b * TT) * HH + h0);
    #pragma unroll
    for (int k = 0; k < TILE_FLOATS / 4 / NTHR; k++) {   // 8 iters
        int i4 = k * NTHR + tid;
        int t = i4 >> 1, q = i4 & 1;
        float4 d = up4[(size_t)t * (HH / 4) + q];
        int c0 = q * 4;
        S[swz(t, c0 + 0)] = d.x;
        S[swz(t, c0 + 1)] = d.y;
        S[swz(t, c0 + 2)] = d.z;
        S[swz(t, c0 + 3)] = d.w;
    }
    __syncthreads();

    // ---- gather this thread's 32 time steps of channel wrp (conflict-free) ----
    float v[32];
    #pragma unroll
    for (int j = 0; j < 32; j++)
        v[j] = S[(lane << 8) + (((j << 3) + wrp) ^ lane)];

    // ---- decay powers A_l = tau^(2^l), squaring chain (exact as JAX) ----
    float A[10];
    A[0] = fminf(fmaxf(alpha[h0 + wrp], 0.0f), 1.0f);
    #pragma unroll
    for (int s = 1; s < 10; s++) A[s] = __fmul_rn(A[s - 1], A[s - 1]);
    tree_scan(v, A, lane);                // v <- x (synaptic current)

    A[0] = fminf(fmaxf(beta[h0 + wrp], 0.0f), 1.0f);
    #pragma unroll
    for (int s = 1; s < 10; s++) A[s] = __fmul_rn(A[s - 1], A[s - 1]);
    tree_scan(v, A, lane);                // v <- V (membrane potential)

    // ---- write V back (each warp touches only its own channel's slots) ----
    #pragma unroll
    for (int j = 0; j < 32; j++)
        S[(lane << 8) + (((j << 3) + wrp) ^ lane)] = v[j];
    __syncthreads();

    // ---- elementwise + threefry + output in flat coalesced layout ----
    const unsigned k2   = (unsigned)seedp[0];    // key=(0,seed): ks0=0
    const unsigned ks1  = k2;
    const unsigned ks2v = k2 ^ 0x1BD11BDAu;
    float* outp = out + ((size_t)b * TT) * HH + h0;

    #pragma unroll 2
    for (int k = 0; k < TILE_FLOATS / 4 / NTHR; k++) {
        int i4 = k * NTHR + tid;
        int t = i4 >> 1, q = i4 & 1;
        int c0 = q * 4;
        float r[4];
        #pragma unroll
        for (int i = 0; i < 4; i++) {
            float V = S[swz(t, c0 + i)];
            float U = __fadd_rn(V, -1.0f);                       // V - THRESHOLD
            float cv  = cosf(__fmul_rn(6.2831855f, U));          // cos(f32(2pi)*U)
            float th  = tanh_xla(__fmul_rn(50.0f, U));           // logistic(100U)
            float sig = __fadd_rn(__fmul_rn(0.5f, th), 0.5f);
            float p   = fmaxf(__fmul_rn(cv, sig), 0.0f);

            unsigned gi = (unsigned)(b * TT + t) * (unsigned)HH + (unsigned)(h0 + c0 + i);
            // threefry2x32(key=(0,seed), counts=(0, gi)); fold out0^out1.
            // The 20 per-round adds go through IMAD (fma pipe) to balance
            // against SHF/LOP3 (alu pipe). Integer math — bit-exact.
            unsigned x0 = 0u;
            unsigned x1 = gi + ks1;
            #define TFR(r_) { x0 = addi(x1, one, x0); x1 = rotl32(x1, (r_)); x1 ^= x0; }
            TFR(13) TFR(15) TFR(26) TFR(6)   x0 += ks1;  x1 += ks2v + 1u;
            TFR(17) TFR(29) TFR(16) TFR(24)  x0 += ks2v; x1 += 2u;
            TFR(13) TFR(15) TFR(26) TFR(6)                x1 += ks1 + 3u;
            TFR(17) TFR(29) TFR(16) TFR(24)  x0 += ks1;  x1 += ks2v + 4u;
            TFR(13) TFR(15) TFR(26) TFR(6)   x0 += ks2v; x1 += 5u;
            #undef TFR
            unsigned bits = x0 ^ x1;
            float uf = __fadd_rn(__uint_as_float((bits >> 9) | 0x3F800000u), -1.0f);
            r[i] = (uf < p) ? 1.0f : 0.0f;
        }
        *reinterpret_cast<float4*>(outp + (size_t)t * HH + c0) =
            make_float4(r[0], r[1], r[2], r[3]);
    }
}

extern "C" void kernel_launch(void* const* d_in, const int* in_sizes, int n_in,
                              void* d_out, int out_size) {
    const float* u     = (const float*)d_in[0];
    const float* alpha = (const float*)d_in[1];
    const float* beta  = (const float*)d_in[2];
    const int*   seed  = (const int*)d_in[3];
    float* out = (float*)d_out;
    (void)in_sizes; (void)n_in; (void)out_size;

    dim3 grid(BB * (HH / HC));   // 4096 CTAs
    cubalif_kernel<<<grid, NTHR>>>(u, alpha, beta, seed, out, 1u);
}